// round 8
// baseline (speedup 1.0000x reference)
#include <cuda_runtime.h>
#include <math.h>

#define NB 16
#define NM 64
#define NC 80
#define CH 85

#define L0_CELLS 307200
#define L1_CELLS 76800
#define L2_CELLS 19200

// obj blocks: 300 + 75 + 19 = 394 ; match blocks: 48 ; total 442
#define OBJ_BLOCKS   394
#define MATCH_BLOCKS 48
#define GRID_BLOCKS  (OBJ_BLOCKS + MATCH_BLOCKS)

// per layer 5 slots: [npos, cls_sum, bbox_sum, obj_corr, obj_sum]
__device__ double g_acc[16];           // zero-initialized at load; self-cleaned each run
__device__ unsigned int g_done = 0;    // ticket counter; self-cleaned each run

__device__ __forceinline__ float softplusf(float x) {
    return fmaxf(x, 0.f) + log1pf(expf(-fabsf(x)));
}

__global__ void __launch_bounds__(256) fused_k(
        const float* __restrict__ p3,
        const float* __restrict__ p4,
        const float* __restrict__ p5,
        const float* __restrict__ boxes,
        const int*   __restrict__ labels,
        const unsigned char* __restrict__ valid,
        const float* __restrict__ anchors,
        float* __restrict__ out) {

    int bid = blockIdx.x;
    int tid = threadIdx.x;

    if (bid < OBJ_BLOCKS) {
        // ---------------- objectness softplus reduction ----------------
        int l, lblk, cells;
        const float* pred;
        if (bid < 300)      { l = 0; lblk = bid;       cells = L0_CELLS; pred = p3; }
        else if (bid < 375) { l = 1; lblk = bid - 300; cells = L1_CELLS; pred = p4; }
        else                { l = 2; lblk = bid - 375; cells = L2_CELLS; pred = p5; }

        int base = lblk * 1024 + tid * 4;
        float s = 0.f;
#pragma unroll
        for (int k = 0; k < 4; k++) {
            int cell = base + k;
            if (cell < cells)
                s += softplusf(__ldg(pred + (size_t)cell * CH + 4));
        }

        __shared__ float sh[256];
        sh[tid] = s;
        __syncthreads();
        for (int st = 128; st > 0; st >>= 1) {
            if (tid < st) sh[tid] += sh[tid + st];
            __syncthreads();
        }
        if (tid == 0)
            atomicAdd(&g_acc[l * 5 + 4], (double)sh[0]);
    } else {
        // ---------------- match block: one (layer, batch) group of 64 boxes ----------------
        int g = bid - OBJ_BLOCKS;       // 0..47
        int l = g >> 4;                 // 0..2
        int b = g & 15;                 // 0..15
        int gw = 80 >> l;
        int gh = 80 >> l;

        __shared__ int    scell[NM];
        __shared__ double s_cls, s_bbox, s_corr;
        __shared__ int    s_npos;
        if (tid == 0) { s_cls = 0.0; s_bbox = 0.0; s_corr = 0.0; s_npos = 0; }
        __syncthreads();

        int m = tid;                    // only threads 0..63 active
        bool pos = false;
        int  cell = -1;
        float cx = 0, cy = 0, w = 0, h = 0;
        const float* row = nullptr;
        const float* pred = (l == 0) ? p3 : ((l == 1) ? p4 : p5);

        if (m < NM) {
            int bm = b * NM + m;
            const float* bx = boxes + (size_t)bm * 4;
            float x1 = bx[0], y1 = bx[1], x2 = bx[2], y2 = bx[3];
            cx = (x1 + x2) * 0.5f * (float)gw;
            cy = (y1 + y2) * 0.5f * (float)gh;
            w  = (x2 - x1) * (float)gw;
            h  = (y2 - y1) * (float)gh;

            float best = -1.0f; int ba = 0;
#pragma unroll
            for (int a = 0; a < 3; a++) {
                float aw = anchors[l * 6 + a * 2 + 0];
                float ah = anchors[l * 6 + a * 2 + 1];
                float inter = fminf(w, aw) * fminf(h, ah);
                float uni   = w * h + aw * ah - inter;
                float iou   = inter / (uni + 1e-6f);
                if (iou > best) { best = iou; ba = a; }
            }
            pos = (valid[bm] != 0) && (best > 0.5f);
            if (pos) {
                int gx = min(max((int)cx, 0), gw - 1);
                int gy = min(max((int)cy, 0), gh - 1);
                cell = ((b * 3 + ba) * gh + gy) * gw + gx;
                row  = pred + (size_t)cell * CH;
            }
        }
        if (tid < NM) scell[tid] = pos ? cell : -1;
        __syncthreads();

        if (pos) {
            // dedup within the group: first occurrence owns the obj correction
            bool is_first = true;
            for (int j = 0; j < m; j++)
                if (scell[j] == cell) { is_first = false; break; }

            atomicAdd(&s_npos, 1);
            if (is_first)
                atomicAdd(&s_corr, -(double)row[4]);

            // classification BCE over 80 classes vs onehot(label)
            int lab = labels[b * NM + m];
            float cls = 0.f;
#pragma unroll 4
            for (int c = 0; c < NC; c++) {
                float xl = row[5 + c];
                float tt = (c == lab) ? 1.f : 0.f;
                cls += fmaxf(xl, 0.f) - xl * tt + log1pf(expf(-fabsf(xl)));
            }
            atomicAdd(&s_cls, (double)cls);

            // CIoU loss (matches reference)
            float pcx = row[0], pcy = row[1], pw = row[2], ph = row[3];
            float px1 = pcx - pw * 0.5f, py1 = pcy - ph * 0.5f;
            float px2 = pcx + pw * 0.5f, py2 = pcy + ph * 0.5f;
            float tx1 = cx - w * 0.5f,  ty1 = cy - h * 0.5f;
            float tx2 = cx + w * 0.5f,  ty2 = cy + h * 0.5f;

            float ix1 = fmaxf(px1, tx1), iy1 = fmaxf(py1, ty1);
            float ix2 = fminf(px2, tx2), iy2 = fminf(py2, ty2);
            float inter = fmaxf(ix2 - ix1, 0.f) * fmaxf(iy2 - iy1, 0.f);
            float a1 = (px2 - px1) * (py2 - py1);
            float a2 = (tx2 - tx1) * (ty2 - ty1);
            float iou = inter / (a1 + a2 - inter + 1e-7f);
            float ccx = (px1 + px2) * 0.5f, ccy = (py1 + py2) * 0.5f;
            float dcx = (tx1 + tx2) * 0.5f, dcy = (ty1 + ty2) * 0.5f;
            float cd = (ccx - dcx) * (ccx - dcx) + (ccy - dcy) * (ccy - dcy);
            float ex1 = fminf(px1, tx1), ey1 = fminf(py1, ty1);
            float ex2 = fmaxf(px2, tx2), ey2 = fmaxf(py2, ty2);
            float dd = (ex2 - ex1) * (ex2 - ex1) + (ey2 - ey1) * (ey2 - ey1);
            float bbl = 1.f - (iou - cd / (dd + 1e-7f));
            atomicAdd(&s_bbox, (double)bbl);
        }
        __syncthreads();

        if (tid == 0) {
            if (s_npos > 0) {
                atomicAdd(&g_acc[l * 5 + 0], (double)s_npos);
                atomicAdd(&g_acc[l * 5 + 1], s_cls);
                atomicAdd(&g_acc[l * 5 + 2], s_bbox);
                atomicAdd(&g_acc[l * 5 + 3], s_corr);
            }
        }
    }

    // ---------------- last block finalizes ----------------
    __shared__ unsigned int s_ticket;
    __threadfence();
    __syncthreads();
    if (tid == 0)
        s_ticket = atomicAdd(&g_done, 1u);
    __syncthreads();

    if (tid == 0 && s_ticket == GRID_BLOCKS - 1) {
        const double cellsd[3] = {(double)L0_CELLS, (double)L1_CELLS, (double)L2_CELLS};
        double total = 0.0;
        for (int l = 0; l < 3; l++) {
            double np = g_acc[l * 5 + 0];
            if (np > 0.0) {
                double denom = (np < 1.0) ? 1.0 : np;
                double cls = g_acc[l * 5 + 1] / (denom * (double)NC);
                double bb  = g_acc[l * 5 + 2] / denom;
                double obj = (g_acc[l * 5 + 4] + g_acc[l * 5 + 3]) / cellsd[l];
                total += 0.5 * cls + 1.0 * obj + 0.05 * bb;
            }
        }
        *out = (float)total;
        // self-clean for deterministic graph replay
        for (int i = 0; i < 16; i++) g_acc[i] = 0.0;
        __threadfence();
        g_done = 0u;
    }
}

extern "C" void kernel_launch(void* const* d_in, const int* in_sizes, int n_in,
                              void* d_out, int out_size) {
    const float* p3 = (const float*)d_in[0];
    const float* p4 = (const float*)d_in[1];
    const float* p5 = (const float*)d_in[2];
    const float* boxes = (const float*)d_in[3];
    const int*   labels = (const int*)d_in[4];
    const unsigned char* valid = (const unsigned char*)d_in[5];
    const float* anchors = (const float*)d_in[6];
    float* out = (float*)d_out;

    fused_k<<<GRID_BLOCKS, 256>>>(p3, p4, p5, boxes, labels, valid, anchors, out);
}